// round 12
// baseline (speedup 1.0000x reference)
#include <cuda_runtime.h>
#include <cuda_fp16.h>
#include <cstdint>

#define NHID     128
#define KDIM     256
#define TILE_M   128
#define THREADS  256
#define NCTAS    2
#define GRID     (152 * NCTAS)
#define NCHUNKS  4       // 64-wide k chunks
#define AROW     144     // bytes per staged edge row (64 fp16 = 128B + 16B pad)

// ---------------- smem layout (bytes, per CTA) ----------------
#define OFF_BFRAG  0
#define OFF_AF0    65536
#define OFF_AF1    83968
#define OFF_SB1    102400
#define OFF_SW2    102912
#define OFF_SRED   103424
#define SMEM_TOTAL 105472

// ---------------- PTX helpers ----------------
__device__ __forceinline__ uint32_t smem_u32(const void* p) {
    uint32_t a;
    asm("{ .reg .u64 t; cvta.to.shared.u64 t, %1; cvt.u32.u64 %0, t; }" : "=r"(a) : "l"(p));
    return a;
}
__device__ __forceinline__ uint32_t f2h2(float lo, float hi) {
    uint32_t v;
    asm("cvt.rn.f16x2.f32 %0, %1, %2;" : "=r"(v) : "f"(hi), "f"(lo));
    return v;
}
__device__ __forceinline__ void sts64(uint32_t addr, uint32_t v0, uint32_t v1) {
    asm volatile("st.shared.v2.b32 [%0], {%1, %2};" :: "r"(addr), "r"(v0), "r"(v1) : "memory");
}
__device__ __forceinline__ void ldsm4(uint32_t* r, uint32_t addr) {
    asm volatile("ldmatrix.sync.aligned.m8n8.x4.shared.b16 {%0,%1,%2,%3}, [%4];"
                 : "=r"(r[0]), "=r"(r[1]), "=r"(r[2]), "=r"(r[3]) : "r"(addr));
}
__device__ __forceinline__ void mma_f16(float& c0, float& c1, float& c2, float& c3,
                                        uint32_t a0, uint32_t a1, uint32_t a2, uint32_t a3,
                                        uint32_t b0, uint32_t b1) {
    asm volatile("mma.sync.aligned.m16n8k16.row.col.f32.f16.f16.f32 "
                 "{%0,%1,%2,%3}, {%4,%5,%6,%7}, {%8,%9}, {%0,%1,%2,%3};"
                 : "+f"(c0), "+f"(c1), "+f"(c2), "+f"(c3)
                 : "r"(a0), "r"(a1), "r"(a2), "r"(a3), "r"(b0), "r"(b1));
}
__device__ __forceinline__ void bar_half(int id) {
    asm volatile("bar.sync %0, %1;" :: "r"(id), "r"(128) : "memory");
}

// ---------------- index width autodetect ----------------
__device__ int g_idx_is64;
__global__ void detect_idx_width(const long long* xi, int n_nodes) {
    int is64 = 1;
    for (int i = 0; i < 16; ++i) {
        long long v = xi[i];
        if (v < 0 || v >= (long long)n_nodes) { is64 = 0; break; }
    }
    g_idx_is64 = is64;
}

// ---------------- main kernel ----------------
extern __shared__ char smem[];

__global__ void __launch_bounds__(THREADS, NCTAS)
mlp_decoder_h7(const float* __restrict__ inputs,
               const void*  __restrict__ x_idx_raw,
               const void*  __restrict__ y_idx_raw,
               const float* __restrict__ W1,
               const float* __restrict__ bias1,
               const float* __restrict__ W2,
               const float* __restrict__ bias2,
               float* __restrict__ out,
               int n_edges)
{
    const int tid  = threadIdx.x;
    const int wid  = tid >> 5;
    const int lane = tid & 31;
    const int g    = lane >> 2;
    const int t    = lane & 3;
    const int mw   = tid >> 7;       // half-CTA / m-group (0..1)
    const int nw   = wid & 3;        // n-group (0..3)
    const int gtid = tid & 127;
    const int barid = mw + 1;
    const uint32_t sbase = smem_u32(smem);

    float* sb1  = (float*)(smem + OFF_SB1);
    float* sw2  = (float*)(smem + OFF_SW2);
    float* sred = (float*)(smem + OFF_SRED);

    // branch-free index load: int64 low word == value for idx < 2^31
    const int ishift = g_idx_is64 ? 3 : 2;
    const char* xraw = (const char*)x_idx_raw;
    const char* yraw = (const char*)y_idx_raw;
    const int emax = n_edges - 1;

    // ---- one-time: W1 -> fp16 B fragment table (whole CTA) ----
    for (int i = tid; i < 16 * 16 * 32; i += THREADS) {
        int nt = i >> 9, ks = (i >> 5) & 15, l = i & 31;
        int gg = l >> 2, tt = l & 3;
        int k0 = ks * 16 + 2 * tt, n = nt * 8 + gg;
        uint32_t b0 = f2h2(W1[k0 * NHID + n],       W1[(k0 + 1) * NHID + n]);
        uint32_t b1 = f2h2(W1[(k0 + 8) * NHID + n], W1[(k0 + 9) * NHID + n]);
        *(uint2*)(smem + OFF_BFRAG + (size_t)i * 8) = make_uint2(b0, b1);
    }
    for (int i = tid; i < NHID; i += THREADS) { sb1[i] = bias1[i]; sw2[i] = W2[i]; }
    const float b2 = bias2[0];

    __syncthreads();   // only full-CTA barrier

    const int ge_l = gtid >> 4;     // 0..7
    const int gq   = gtid & 15;     // float4 slot within 64-float chunk
    const uint32_t lm_off = (uint32_t)(lane & 15) * AROW + (uint32_t)(lane >> 4) * 16;

    float4 pf[4];
    // prefetch half h (32 owned edges) of chunk c for tile at ebase_
    auto prefetch = [&](int ebase_, int c, int h) {
        const char* ip = (c < 2) ? xraw : yraw;
        const int kbase = (c & 1) * 64;
        int node[4];
        #pragma unroll
        for (int r = 0; r < 4; ++r) {
            int e = ebase_ + mw * 64 + h * 32 + r * 8 + ge_l;
            if (e > emax) e = emax;
            node[r] = *(const int*)(ip + ((size_t)(unsigned)e << ishift));
        }
        #pragma unroll
        for (int r = 0; r < 4; ++r)
            pf[r] = *(const float4*)(inputs + (size_t)node[r] * NHID + kbase + gq * 4);
    };
    auto sts_half = [&](int c, int h) {
        const uint32_t abuf = sbase + ((c & 1) ? OFF_AF1 : OFF_AF0);
        #pragma unroll
        for (int r = 0; r < 4; ++r) {
            int j = mw * 64 + h * 32 + r * 8 + ge_l;
            sts64(abuf + (uint32_t)j * AROW + (uint32_t)gq * 8,
                  f2h2(pf[r].x, pf[r].y), f2h2(pf[r].z, pf[r].w));
        }
    };

    const int ntiles = (n_edges + TILE_M - 1) / TILE_M;

    // prologue: prefetch first tile's chunk0/half0
    prefetch(blockIdx.x * TILE_M, 0, 0);

    for (int tile = blockIdx.x; tile < ntiles; tile += GRID) {
        const int ebase = tile * TILE_M;

        // pf holds (this tile, c0, h0)
        sts_half(0, 0);
        prefetch(ebase, 0, 1); sts_half(0, 1);
        bar_half(barid);

        float acc[4][4][4];
        #pragma unroll
        for (int mt = 0; mt < 4; ++mt)
            #pragma unroll
            for (int nt = 0; nt < 4; ++nt)
                #pragma unroll
                for (int r = 0; r < 4; ++r) acc[mt][nt][r] = 0.0f;

        for (int c = 0; c < NCHUNKS; ++c) {
            const uint32_t abuf = sbase + ((c & 1) ? OFF_AF1 : OFF_AF0);

            if (c < NCHUNKS - 1) prefetch(ebase, c + 1, 0);

            #pragma unroll
            for (int ks = 0; ks < 4; ++ks) {
                if (ks == 2) {
                    if (c < NCHUNKS - 1) {          // commit h0, launch h1
                        sts_half(c + 1, 0);
                        prefetch(ebase, c + 1, 1);
                    } else if (tile + GRID < ntiles) {
                        // cross-tile: next tile's chunk0/half0 (A buf0 is free)
                        prefetch(ebase + GRID * TILE_M, 0, 0);
                    }
                }
                const int gks = c * 4 + ks;
                uint2 bf[4];
                #pragma unroll
                for (int nt = 0; nt < 4; ++nt)
                    bf[nt] = *(const uint2*)(smem + OFF_BFRAG +
                              (size_t)(((nw * 4 + nt) * 16 + gks) * 32 + lane) * 8);
                // rolling ldsm pipeline over mt
                uint32_t A0[4], A1[4];
                ldsm4(A0, abuf + (uint32_t)((mw * 4) * 16) * AROW
                              + (uint32_t)ks * 32 + lm_off);
                #pragma unroll
                for (int mt = 0; mt < 4; ++mt) {
                    uint32_t* cur = (mt & 1) ? A1 : A0;
                    if (mt < 3) {
                        uint32_t* nxt = (mt & 1) ? A0 : A1;
                        ldsm4(nxt, abuf + (uint32_t)((mw * 4 + mt + 1) * 16) * AROW
                                        + (uint32_t)ks * 32 + lm_off);
                    }
                    #pragma unroll
                    for (int nt = 0; nt < 4; ++nt)
                        mma_f16(acc[mt][nt][0], acc[mt][nt][1],
                                acc[mt][nt][2], acc[mt][nt][3],
                                cur[0], cur[1], cur[2], cur[3], bf[nt].x, bf[nt].y);
                }
            }

            if (c < NCHUNKS - 1) {
                sts_half(c + 1, 1);
                bar_half(barid);
            }
        }

        // ---- epilogue (per half): relu + W2 dot, reduce lanes/groups ----
        #pragma unroll
        for (int mt = 0; mt < 4; ++mt) {
            #pragma unroll
            for (int h = 0; h < 2; ++h) {
                float s = 0.0f;
                #pragma unroll
                for (int nt = 0; nt < 4; ++nt) {
                    int col = (nw * 4 + nt) * 8 + t * 2;
                    float ca = acc[mt][nt][h * 2];
                    float cb = acc[mt][nt][h * 2 + 1];
                    s += fmaxf(ca + sb1[col],     0.0f) * sw2[col];
                    s += fmaxf(cb + sb1[col + 1], 0.0f) * sw2[col + 1];
                }
                s += __shfl_xor_sync(0xffffffffu, s, 1);
                s += __shfl_xor_sync(0xffffffffu, s, 2);
                if (t == 0) {
                    int row = (mw * 4 + mt) * 16 + g + h * 8;
                    sred[row * 4 + nw] = s;
                }
            }
        }
        bar_half(barid);

        if (gtid < 64) {
            int row = mw * 64 + gtid;
            float4 v = *(const float4*)(sred + row * 4);
            float sum = (v.x + v.y) + (v.z + v.w) + b2;
            int e = ebase + row;
            if (e < n_edges)
                out[e] = 1.0f / (1.0f + __expf(-sum));
        }
        // no trailing barrier: sred/buf0 hazards are covered by the chunk
        // barriers and post-sred barrier of the NEXT tile's pipeline.
    }
}

// ---------------- launch ----------------
extern "C" void kernel_launch(void* const* d_in, const int* in_sizes, int n_in,
                              void* d_out, int out_size)
{
    const float* inputs = (const float*)d_in[0];
    const void*  x_idx  = d_in[1];
    const void*  y_idx  = d_in[2];
    const float* W1     = (const float*)d_in[3];
    const float* bias1  = (const float*)d_in[4];
    const float* W2     = (const float*)d_in[5];
    const float* bias2  = (const float*)d_in[6];
    float* out = (float*)d_out;

    const int n_edges = in_sizes[1];
    const int n_nodes = in_sizes[0] / NHID;

    detect_idx_width<<<1, 1>>>((const long long*)x_idx, n_nodes);

    cudaFuncSetAttribute(mlp_decoder_h7,
                         cudaFuncAttributeMaxDynamicSharedMemorySize, SMEM_TOTAL);
    mlp_decoder_h7<<<GRID, THREADS, SMEM_TOTAL>>>(
        inputs, x_idx, y_idx, W1, bias1, W2, bias2, out, n_edges);
}